// round 15
// baseline (speedup 1.0000x reference)
#include <cuda_runtime.h>
#include <cuda_bf16.h>
#include <math.h>
#include <stdint.h>

// Problem: B=8, S=1024, D=1024 -> N=8192 points, dim 1024.
// R14 resubmission (R14 never executed: broker-level container flake; the
// unchanged-resubmission pattern has passed 3/3 times so far).
#define NPTS 8192
#define DIM  1024
#define TI   128
#define TJ   128
#define BK   32                          // k per chunk (bf16) -> 16KB/stage
#define CPT  (DIM / BK)                  // 32 chunks per j-tile
#define NSTRIPS 8
#define JSTRIP (NPTS / NSTRIPS)          // 1024 j per CTA
#define NTILES (JSTRIP / TJ)             // 8 j-tiles per CTA
#define CHUNKS (NTILES * CPT)            // 256 chunks per CTA
#define STAGE   16384                    // A 8KB + B 8KB
#define KSEL 5
#define P_THRESH 0.1f
#define TAU 32.0f

__device__ float g_sq[NPTS];
__device__ float g_part[NPTS * NSTRIPS * KSEL];   // top-5 d^2 per strip
__device__ float g_w[NPTS];
__device__ uint4 g_xbf4[NPTS * DIM / 8];          // bf16 x_real, 8 per uint4

__device__ __forceinline__ uint32_t smaddr(const void* p) {
    return (uint32_t)__cvta_generic_to_shared(p);
}

// sorted ascending 5-array insertion
__device__ __forceinline__ void ins5(float (&tk)[KSEL], float v) {
    if (v < tk[4]) {
        tk[4] = v;
        if (tk[4] < tk[3]) { float t = tk[3]; tk[3] = tk[4]; tk[4] = t; }
        if (tk[3] < tk[2]) { float t = tk[2]; tk[2] = tk[3]; tk[3] = t; }
        if (tk[2] < tk[1]) { float t = tk[1]; tk[1] = tk[2]; tk[2] = t; }
        if (tk[1] < tk[0]) { float t = tk[0]; tk[0] = tk[1]; tk[1] = t; }
    }
}

// packed layout for 64B (BK=32) rows: two rows per 128B line.
// row r, unit u(0..3): offset = (r>>1)*128 + ((((r&1)*4+u) ^ ((r>>1)&7)) * 16)
// Conflict-free for the fill (32 distinct 16B units per warp) and for
// ldmatrix 8-row groups (8 distinct (line,lane) pairs).
__device__ __forceinline__ uint32_t pk_off(int r, int u) {
    return (uint32_t)(((r >> 1) << 7) + (((((r & 1) << 2) + u) ^ ((r >> 1) & 7)) << 4));
}

// ---------------- K1: fused bf16 convert + row norms ----------------
__global__ void prep_kernel(const float* __restrict__ xr) {
    const int row = blockIdx.x;
    const int t = threadIdx.x;                  // 128 threads x 8 elems
    const size_t base = (size_t)row * DIM + t * 8;
    const float4 f0 = *(const float4*)&xr[base];
    const float4 f1 = *(const float4*)&xr[base + 4];
    float fs[8] = {f0.x, f0.y, f0.z, f0.w, f1.x, f1.y, f1.z, f1.w};
    float s = 0.f;
    uint32_t ws[4];
    #pragma unroll
    for (int q = 0; q < 4; q++) {
        s += fs[2*q] * fs[2*q] + fs[2*q+1] * fs[2*q+1];
        __nv_bfloat16 lo = __float2bfloat16_rn(fs[2*q]);
        __nv_bfloat16 hi = __float2bfloat16_rn(fs[2*q+1]);
        ws[q] = ((uint32_t)(*(uint16_t*)&hi) << 16) | (uint32_t)(*(uint16_t*)&lo);
    }
    uint4 o; o.x = ws[0]; o.y = ws[1]; o.z = ws[2]; o.w = ws[3];
    g_xbf4[row * (DIM / 8) + t] = o;
    #pragma unroll
    for (int off = 16; off > 0; off >>= 1) s += __shfl_down_sync(0xffffffffu, s, off);
    __shared__ float red[4];
    if ((t & 31) == 0) red[t >> 5] = s;
    __syncthreads();
    if (t == 0) g_sq[row] = red[0] + red[1] + red[2] + red[3];
}

// ---------------- K2: HMMA distance GEMM + online top-5 ----------------
// 512 thr = 16 warps (4M x 4N), warp tile 32x32, block tile 128x128.
// DOUBLE-BUFFERED smem (BK=32, 2x16KB stages): one __syncthreads per chunk,
// STS of chunk c+1 and LDG prefetch of c+2 overlap compute of chunk c.
__global__ __launch_bounds__(512, 1)
void dist_topk_kernel() {
    __shared__ __align__(16) uint8_t smraw[40960];  // 2 stages (32KB) / merge (40KB)
    float* cand = (float*)smraw;

    const int t = threadIdx.x;
    const int lane = t & 31;
    const int warp = t >> 5;                      // 0..15
    const int warpM = warp >> 2;                  // 0..3 (32-row strips)
    const int warpN = warp & 3;                   // 0..3 (32-col strips)
    const int strip = blockIdx.x;
    const int iBase = blockIdx.y * TI;
    const uint32_t smBase = smaddr(smraw);

    float tk[4][KSEL];
    #pragma unroll
    for (int r = 0; r < 4; r++)
        #pragma unroll
        for (int s = 0; s < KSEL; s++) tk[r][s] = 1e30f;

    float sqi[4];
    #pragma unroll
    for (int r4 = 0; r4 < 4; r4++) {
        const int mt = r4 >> 1, h = r4 & 1;
        sqi[r4] = g_sq[iBase + warpM * 32 + mt * 16 + h * 8 + (lane >> 2)];
    }

    // precompute ldmatrix offsets within a stage (A at +0, B at +8192)
    const int grp = lane >> 3, rIn = lane & 7;
    const int lg = lane & 15;
    uint32_t offA[2][2], offB[4][2];
    #pragma unroll
    for (int mt = 0; mt < 2; mt++) {
        const int row = warpM * 32 + mt * 16 + ((grp & 1) << 3) + rIn;
        #pragma unroll
        for (int s = 0; s < 2; s++)
            offA[mt][s] = pk_off(row, (s << 1) + (grp >> 1));
    }
    #pragma unroll
    for (int nt = 0; nt < 4; nt++) {
        const int row = warpN * 32 + nt * 8 + (lg & 7);
        #pragma unroll
        for (int s = 0; s < 2; s++)
            offB[nt][s] = 8192u + pk_off(row, (s << 1) + (lg >> 3));
    }

    // fill: 512 threads -> row = t>>2 (0..127), unit u = t&3 (one uint4 each)
    const int ldRow = t >> 2;
    const int ldU = t & 3;
    const uint32_t fillOff = pk_off(ldRow, ldU);

    uint4 pa, pb;
    auto prefetch = [&](int c) {
        const int jt = c >> 5, kc = c & 31;          // kc in K32 units
        pa = g_xbf4[(size_t)(iBase + ldRow) * (DIM / 8) + kc * 4 + ldU];
        const int jB = strip * JSTRIP + jt * TJ;
        pb = g_xbf4[(size_t)(jB + ldRow) * (DIM / 8) + kc * 4 + ldU];
    };
    auto store_stage = [&](int c) {
        const uint32_t off = (uint32_t)(c & 1) * STAGE;
        *(uint4*)((char*)smraw + off + fillOff) = pa;
        *(uint4*)((char*)smraw + off + 8192 + fillOff) = pb;
    };

    prefetch(0);
    store_stage(0);
    __syncthreads();
    prefetch(1);

    float acc[2][4][4];
    #pragma unroll
    for (int mt = 0; mt < 2; mt++)
        #pragma unroll
        for (int nt = 0; nt < 4; nt++)
            #pragma unroll
            for (int q = 0; q < 4; q++) acc[mt][nt][q] = 0.0f;

    for (int c = 0; c < CHUNKS; c++) {
        // overlap: store next chunk into the other buffer, prefetch chunk+2
        if (c + 1 < CHUNKS) store_stage(c + 1);
        if (c + 2 < CHUNKS) prefetch(c + 2);

        const uint32_t sb = smBase + (uint32_t)(c & 1) * STAGE;
        #pragma unroll
        for (int s = 0; s < 2; s++) {          // 2 k16 steps per K32 chunk
            uint32_t af[2][4];
            #pragma unroll
            for (int mt = 0; mt < 2; mt++)
                asm volatile(
                    "ldmatrix.sync.aligned.m8n8.x4.shared.b16 {%0,%1,%2,%3}, [%4];"
                    : "=r"(af[mt][0]), "=r"(af[mt][1]),
                      "=r"(af[mt][2]), "=r"(af[mt][3])
                    : "r"(sb + offA[mt][s]));
            uint32_t bfr[4][2];
            #pragma unroll
            for (int nt = 0; nt < 4; nt++)
                asm volatile(
                    "ldmatrix.sync.aligned.m8n8.x2.shared.b16 {%0,%1}, [%2];"
                    : "=r"(bfr[nt][0]), "=r"(bfr[nt][1])
                    : "r"(sb + offB[nt][s]));
            #pragma unroll
            for (int mt = 0; mt < 2; mt++)
                #pragma unroll
                for (int nt = 0; nt < 4; nt++)
                    asm volatile(
                        "mma.sync.aligned.m16n8k16.row.col.f32.bf16.bf16.f32 "
                        "{%0,%1,%2,%3}, {%4,%5,%6,%7}, {%8,%9}, {%0,%1,%2,%3};"
                        : "+f"(acc[mt][nt][0]), "+f"(acc[mt][nt][1]),
                          "+f"(acc[mt][nt][2]), "+f"(acc[mt][nt][3])
                        : "r"(af[mt][0]), "r"(af[mt][1]),
                          "r"(af[mt][2]), "r"(af[mt][3]),
                          "r"(bfr[nt][0]), "r"(bfr[nt][1]));
        }

        if ((c & 31) == 31) {
            // end of j-tile: register-only epilogue, d^2 -> top-5
            const int jt = c >> 5;
            const int jBase = strip * JSTRIP + jt * TJ;
            #pragma unroll
            for (int nt = 0; nt < 4; nt++) {
                const int j0 = jBase + warpN * 32 + nt * 8 + ((lane & 3) << 1);
                const float sq0 = g_sq[j0];
                const float sq1 = g_sq[j0 + 1];
                #pragma unroll
                for (int mt = 0; mt < 2; mt++)
                    #pragma unroll
                    for (int h = 0; h < 2; h++) {
                        const int r4 = mt * 2 + h;
                        const int iRow = iBase + warpM * 32 + mt * 16 + h * 8 + (lane >> 2);
                        float d0 = fmaxf(fmaf(-2.0f, acc[mt][nt][h * 2 + 0], sqi[r4] + sq0), 0.0f);
                        float d1 = fmaxf(fmaf(-2.0f, acc[mt][nt][h * 2 + 1], sqi[r4] + sq1), 0.0f);
                        if (j0 == iRow)     d0 = 1e30f;   // exclude self
                        if (j0 + 1 == iRow) d1 = 1e30f;
                        ins5(tk[r4], d0);
                        ins5(tk[r4], d1);
                        acc[mt][nt][h * 2 + 0] = 0.0f;    // reset for next tile
                        acc[mt][nt][h * 2 + 1] = 0.0f;
                    }
            }
        }

        // single barrier: protects buf(c&1) (just read) from STS(c+2) next iter,
        // and publishes STS(c+1) for compute(c+1).
        __syncthreads();
    }

    // merge 16 candidate lists per row through smem (tiles done -> smem free)
    #pragma unroll
    for (int r4 = 0; r4 < 4; r4++) {
        const int mt = r4 >> 1, h = r4 & 1;
        const int row = warpM * 32 + mt * 16 + h * 8 + (lane >> 2);
        const int slot = warpN * 4 + (lane & 3);
        #pragma unroll
        for (int s = 0; s < KSEL; s++)
            cand[row * (16 * KSEL) + slot * KSEL + s] = tk[r4][s];
    }
    __syncthreads();
    if (t < TI) {
        float best[KSEL] = {1e30f, 1e30f, 1e30f, 1e30f, 1e30f};
        #pragma unroll 4
        for (int q = 0; q < 16 * KSEL; q++)
            ins5(best, cand[t * (16 * KSEL) + q]);
        float* dst = &g_part[(size_t)(iBase + t) * (NSTRIPS * KSEL) + strip * KSEL];
        #pragma unroll
        for (int s = 0; s < KSEL; s++) dst[s] = best[s];
    }
}

// ---------------- K3: merge strips -> weight ----------------
__global__ void finalize_w_kernel() {
    const int i = blockIdx.x * blockDim.x + threadIdx.x;
    if (i >= NPTS) return;
    const float* p = &g_part[(size_t)i * NSTRIPS * KSEL];
    float best[KSEL] = {1e30f, 1e30f, 1e30f, 1e30f, 1e30f};
    #pragma unroll
    for (int q = 0; q < NSTRIPS * KSEL; q++) ins5(best, p[q]);
    const float score = (sqrtf(best[0]) + sqrtf(best[1]) + sqrtf(best[2]) +
                         sqrtf(best[3]) + sqrtf(best[4])) * 0.2f;
    const float w = expf(-score / TAU);
    g_w[i] = (score > P_THRESH) ? w : 0.0f;
}

// ---------------- K4: apply weights ----------------
__global__ void apply_w_kernel(const float* __restrict__ xr,
                               const float* __restrict__ xi,
                               float* __restrict__ out) {
    const int row = blockIdx.x;
    const float w = g_w[row];
    const int t = threadIdx.x;
    const size_t off = (size_t)row * DIM + t * 4;
    float4 a = *(const float4*)&xr[off];
    a.x *= w; a.y *= w; a.z *= w; a.w *= w;
    *(float4*)&out[off] = a;
    float4 b = *(const float4*)&xi[off];
    b.x *= w; b.y *= w; b.z *= w; b.w *= w;
    *(float4*)&out[(size_t)NPTS * DIM + off] = b;
}

extern "C" void kernel_launch(void* const* d_in, const int* in_sizes, int n_in,
                              void* d_out, int out_size) {
    const float* xr = (const float*)d_in[0];
    const float* xi = (const float*)d_in[1];
    float* out = (float*)d_out;

    prep_kernel<<<NPTS, 128>>>(xr);
    dist_topk_kernel<<<dim3(NSTRIPS, NPTS / TI), 512>>>();
    finalize_w_kernel<<<NPTS / 256, 256>>>();
    apply_w_kernel<<<NPTS, 256>>>(xr, xi, out);
}

// round 16
// speedup vs baseline: 1.2135x; 1.2135x over previous
#include <cuda_runtime.h>
#include <cuda_bf16.h>
#include <math.h>
#include <stdint.h>

// Problem: B=8, S=1024, D=1024 -> N=8192 points, dim 1024.
// Base: R13 (695us pass). Changes: NSTRIPS 8->16 (wave quantization fix),
// B fragments via ldmatrix.x4 nt-pairs (LDSM issue count -33%).
#define NPTS 8192
#define DIM  1024
#define TI   128
#define TJ   128
#define BK   64                          // k per chunk (bf16)
#define CPT  (DIM / BK)                  // 16 chunks per j-tile
#define NSTRIPS 16
#define JSTRIP (NPTS / NSTRIPS)          // 512 j per CTA
#define NTILES (JSTRIP / TJ)             // 4 j-tiles per CTA
#define CHUNKS (NTILES * CPT)            // 64 chunks per CTA
#define KSEL 5
#define P_THRESH 0.1f
#define TAU 32.0f

__device__ float g_sq[NPTS];
__device__ float g_part[NPTS * NSTRIPS * KSEL];   // top-5 d^2 per strip
__device__ float g_w[NPTS];
__device__ uint4 g_xbf4[NPTS * DIM / 8];          // bf16 x_real, 8 per uint4

__device__ __forceinline__ uint32_t smaddr(const void* p) {
    return (uint32_t)__cvta_generic_to_shared(p);
}

// sorted ascending 5-array insertion
__device__ __forceinline__ void ins5(float (&tk)[KSEL], float v) {
    if (v < tk[4]) {
        tk[4] = v;
        if (tk[4] < tk[3]) { float t = tk[3]; tk[3] = tk[4]; tk[4] = t; }
        if (tk[3] < tk[2]) { float t = tk[2]; tk[2] = tk[3]; tk[3] = t; }
        if (tk[2] < tk[1]) { float t = tk[1]; tk[1] = tk[2]; tk[2] = t; }
        if (tk[1] < tk[0]) { float t = tk[0]; tk[0] = tk[1]; tk[1] = t; }
    }
}

// ---------------- K1: fused bf16 convert + row norms ----------------
__global__ void prep_kernel(const float* __restrict__ xr) {
    const int row = blockIdx.x;
    const int t = threadIdx.x;                  // 128 threads x 8 elems
    const size_t base = (size_t)row * DIM + t * 8;
    const float4 f0 = *(const float4*)&xr[base];
    const float4 f1 = *(const float4*)&xr[base + 4];
    float fs[8] = {f0.x, f0.y, f0.z, f0.w, f1.x, f1.y, f1.z, f1.w};
    float s = 0.f;
    uint32_t ws[4];
    #pragma unroll
    for (int q = 0; q < 4; q++) {
        s += fs[2*q] * fs[2*q] + fs[2*q+1] * fs[2*q+1];
        __nv_bfloat16 lo = __float2bfloat16_rn(fs[2*q]);
        __nv_bfloat16 hi = __float2bfloat16_rn(fs[2*q+1]);
        ws[q] = ((uint32_t)(*(uint16_t*)&hi) << 16) | (uint32_t)(*(uint16_t*)&lo);
    }
    uint4 o; o.x = ws[0]; o.y = ws[1]; o.z = ws[2]; o.w = ws[3];
    g_xbf4[row * (DIM / 8) + t] = o;
    #pragma unroll
    for (int off = 16; off > 0; off >>= 1) s += __shfl_down_sync(0xffffffffu, s, off);
    __shared__ float red[4];
    if ((t & 31) == 0) red[t >> 5] = s;
    __syncthreads();
    if (t == 0) g_sq[row] = red[0] + red[1] + red[2] + red[3];
}

// ---------------- K2: HMMA distance GEMM + online top-5 ----------------
// 512 thr = 16 warps (4M x 4N), warp tile 32x32, block tile 128x128.
// Single smem buffer (BK=64), register-prefetch double buffering.
// B fragments loaded as ldmatrix.x4 over nt-pairs (full 32-lane usage).
__global__ __launch_bounds__(512, 1)
void dist_topk_kernel() {
    __shared__ __align__(16) uint4 smraw[2560];   // 40KB: tiles (32KB) / merge (40KB)
    uint4* smA = smraw;                           // 128 rows x 8 units, swz u^(row&7)
    uint4* smB = smraw + 1024;
    float* cand = (float*)smraw;

    const int t = threadIdx.x;
    const int lane = t & 31;
    const int warp = t >> 5;                      // 0..15
    const int warpM = warp >> 2;                  // 0..3 (32-row strips)
    const int warpN = warp & 3;                   // 0..3 (32-col strips)
    const int strip = blockIdx.x;                 // 0..15
    const int iBase = blockIdx.y * TI;
    const uint32_t smA_base = smaddr(smA);
    const uint32_t smB_base = smaddr(smB);

    float tk[4][KSEL];
    #pragma unroll
    for (int r = 0; r < 4; r++)
        #pragma unroll
        for (int s = 0; s < KSEL; s++) tk[r][s] = 1e30f;

    float sqi[4];
    #pragma unroll
    for (int r4 = 0; r4 < 4; r4++) {
        const int mt = r4 >> 1, h = r4 & 1;
        sqi[r4] = g_sq[iBase + warpM * 32 + mt * 16 + h * 8 + (lane >> 2)];
    }

    // fill assignment: 512 threads -> row = t>>2 (0..127), units ldU0, ldU0+1
    const int ldRow = t >> 2;
    const int ldU0 = (t & 3) * 2;

    uint4 pa[2], pb[2];
    auto prefetch = [&](int c) {
        const int jt = c >> 4, kc = c & 15;
        const uint4* srcA = g_xbf4 + (size_t)(iBase + ldRow) * (DIM / 8) + kc * 8 + ldU0;
        const int jB = strip * JSTRIP + jt * TJ;
        const uint4* srcB = g_xbf4 + (size_t)(jB + ldRow) * (DIM / 8) + kc * 8 + ldU0;
        #pragma unroll
        for (int q = 0; q < 2; q++) { pa[q] = srcA[q]; pb[q] = srcB[q]; }
    };

    prefetch(0);

    float acc[2][4][4];
    #pragma unroll
    for (int mt = 0; mt < 2; mt++)
        #pragma unroll
        for (int nt = 0; nt < 4; nt++)
            #pragma unroll
            for (int q = 0; q < 4; q++) acc[mt][nt][q] = 0.0f;

    for (int c = 0; c < CHUNKS; c++) {
        // store prefetched chunk c into smem (swizzle identical to validated R3)
        #pragma unroll
        for (int q = 0; q < 2; q++) {
            const int u = ldU0 + q;
            const int swz = u ^ (ldRow & 7);
            smA[(ldRow << 3) + swz] = pa[q];
            smB[(ldRow << 3) + swz] = pb[q];
        }
        __syncthreads();

        if (c + 1 < CHUNKS) prefetch(c + 1);   // hide LDG latency behind MMAs

        #pragma unroll
        for (int s = 0; s < 4; s++) {          // 4 k16 steps per K64 chunk
            uint32_t af[2][4];
            #pragma unroll
            for (int mt = 0; mt < 2; mt++) {
                const int grp = lane >> 3, rIn = lane & 7;
                const int row = warpM * 32 + mt * 16 + ((grp & 1) << 3) + rIn;
                const int ku = (s << 1) + (grp >> 1);
                const uint32_t addr = smA_base + (((row << 3) + (ku ^ (row & 7))) << 4);
                asm volatile(
                    "ldmatrix.sync.aligned.m8n8.x4.shared.b16 {%0,%1,%2,%3}, [%4];"
                    : "=r"(af[mt][0]), "=r"(af[mt][1]),
                      "=r"(af[mt][2]), "=r"(af[mt][3])
                    : "r"(addr));
            }
            // B: one x4 per nt-pair; lane groups (n0,ku0),(n0,ku1),(n1,ku0),(n1,ku1)
            uint32_t bfr[4][2];
            #pragma unroll
            for (int q = 0; q < 2; q++) {
                const int g2 = lane >> 3;                   // 0..3
                const int row = warpN * 32 + (q * 2 + (g2 >> 1)) * 8 + (lane & 7);
                const int ku = (s << 1) + (g2 & 1);
                const uint32_t addr = smB_base + (((row << 3) + (ku ^ (row & 7))) << 4);
                asm volatile(
                    "ldmatrix.sync.aligned.m8n8.x4.shared.b16 {%0,%1,%2,%3}, [%4];"
                    : "=r"(bfr[q * 2][0]),     "=r"(bfr[q * 2][1]),
                      "=r"(bfr[q * 2 + 1][0]), "=r"(bfr[q * 2 + 1][1])
                    : "r"(addr));
            }
            #pragma unroll
            for (int mt = 0; mt < 2; mt++)
                #pragma unroll
                for (int nt = 0; nt < 4; nt++)
                    asm volatile(
                        "mma.sync.aligned.m16n8k16.row.col.f32.bf16.bf16.f32 "
                        "{%0,%1,%2,%3}, {%4,%5,%6,%7}, {%8,%9}, {%0,%1,%2,%3};"
                        : "+f"(acc[mt][nt][0]), "+f"(acc[mt][nt][1]),
                          "+f"(acc[mt][nt][2]), "+f"(acc[mt][nt][3])
                        : "r"(af[mt][0]), "r"(af[mt][1]),
                          "r"(af[mt][2]), "r"(af[mt][3]),
                          "r"(bfr[nt][0]), "r"(bfr[nt][1]));
        }
        __syncthreads();

        if ((c & 15) == 15) {
            // end of j-tile: register-only epilogue, d^2 -> top-5
            const int jt = c >> 4;
            const int jBase = strip * JSTRIP + jt * TJ;
            #pragma unroll
            for (int nt = 0; nt < 4; nt++) {
                const int j0 = jBase + warpN * 32 + nt * 8 + ((lane & 3) << 1);
                const float sq0 = g_sq[j0];
                const float sq1 = g_sq[j0 + 1];
                #pragma unroll
                for (int mt = 0; mt < 2; mt++)
                    #pragma unroll
                    for (int h = 0; h < 2; h++) {
                        const int r4 = mt * 2 + h;
                        const int iRow = iBase + warpM * 32 + mt * 16 + h * 8 + (lane >> 2);
                        float d0 = fmaxf(fmaf(-2.0f, acc[mt][nt][h * 2 + 0], sqi[r4] + sq0), 0.0f);
                        float d1 = fmaxf(fmaf(-2.0f, acc[mt][nt][h * 2 + 1], sqi[r4] + sq1), 0.0f);
                        if (j0 == iRow)     d0 = 1e30f;   // exclude self
                        if (j0 + 1 == iRow) d1 = 1e30f;
                        ins5(tk[r4], d0);
                        ins5(tk[r4], d1);
                        acc[mt][nt][h * 2 + 0] = 0.0f;    // reset for next tile
                        acc[mt][nt][h * 2 + 1] = 0.0f;
                    }
            }
        }
    }

    // merge 16 candidate lists per row through smem (tiles done -> smem free)
    __syncthreads();
    #pragma unroll
    for (int r4 = 0; r4 < 4; r4++) {
        const int mt = r4 >> 1, h = r4 & 1;
        const int row = warpM * 32 + mt * 16 + h * 8 + (lane >> 2);
        const int slot = warpN * 4 + (lane & 3);
        #pragma unroll
        for (int s = 0; s < KSEL; s++)
            cand[row * (16 * KSEL) + slot * KSEL + s] = tk[r4][s];
    }
    __syncthreads();
    if (t < TI) {
        float best[KSEL] = {1e30f, 1e30f, 1e30f, 1e30f, 1e30f};
        #pragma unroll 4
        for (int q = 0; q < 16 * KSEL; q++)
            ins5(best, cand[t * (16 * KSEL) + q]);
        float* dst = &g_part[(size_t)(iBase + t) * (NSTRIPS * KSEL) + strip * KSEL];
        #pragma unroll
        for (int s = 0; s < KSEL; s++) dst[s] = best[s];
    }
}

// ---------------- K3: merge strips -> weight ----------------
__global__ void finalize_w_kernel() {
    const int i = blockIdx.x * blockDim.x + threadIdx.x;
    if (i >= NPTS) return;
    const float* p = &g_part[(size_t)i * NSTRIPS * KSEL];
    float best[KSEL] = {1e30f, 1e30f, 1e30f, 1e30f, 1e30f};
    #pragma unroll
    for (int q = 0; q < NSTRIPS * KSEL; q++) ins5(best, p[q]);
    const float score = (sqrtf(best[0]) + sqrtf(best[1]) + sqrtf(best[2]) +
                         sqrtf(best[3]) + sqrtf(best[4])) * 0.2f;
    const float w = expf(-score / TAU);
    g_w[i] = (score > P_THRESH) ? w : 0.0f;
}

// ---------------- K4: apply weights ----------------
__global__ void apply_w_kernel(const float* __restrict__ xr,
                               const float* __restrict__ xi,
                               float* __restrict__ out) {
    const int row = blockIdx.x;
    const float w = g_w[row];
    const int t = threadIdx.x;
    const size_t off = (size_t)row * DIM + t * 4;
    float4 a = *(const float4*)&xr[off];
    a.x *= w; a.y *= w; a.z *= w; a.w *= w;
    *(float4*)&out[off] = a;
    float4 b = *(const float4*)&xi[off];
    b.x *= w; b.y *= w; b.z *= w; b.w *= w;
    *(float4*)&out[(size_t)NPTS * DIM + off] = b;
}

extern "C" void kernel_launch(void* const* d_in, const int* in_sizes, int n_in,
                              void* d_out, int out_size) {
    const float* xr = (const float*)d_in[0];
    const float* xi = (const float*)d_in[1];
    float* out = (float*)d_out;

    prep_kernel<<<NPTS, 128>>>(xr);
    dist_topk_kernel<<<dim3(NSTRIPS, NPTS / TI), 512>>>();
    finalize_w_kernel<<<NPTS / 256, 256>>>();
    apply_w_kernel<<<NPTS, 256>>>(xr, xi, out);
}